// round 15
// baseline (speedup 1.0000x reference)
#include <cuda_runtime.h>
#include <cuda_fp16.h>
#include <cstdint>

// Problem constants
#define BB 64
#define SS 1024
#define CC 512
#define SC (SS*CC)
#define NN (BB*CC)          // 32768 = total N of the big GEMM
#define EPS 1e-5f
#define RED_CHUNKS 64
#define BK 32               // k-tile (halves)
#define NT (SS / BK)        // 32 k-tiles

// Scratch (device globals; 16B-aligned for cp.async / uint4)
__device__ float2 g_partials[BB * RED_CHUNKS];
__device__ float2 g_stats[BB];
// K-panel layouts: [(kt*ROWS + row)*32 + ks], fp16
__device__ __align__(16) __half g_Hp[(size_t)NN * SS];     // B panels (64MB)
__device__ __align__(16) __half g_Wh[(size_t)SS * SS];     // A panels (2MB)

// ---------------------------------------------------------------------------
// helpers
// ---------------------------------------------------------------------------
__device__ __forceinline__ uint32_t smem_to_u32(const void* p) {
    uint32_t a;
    asm("{ .reg .u64 t; cvta.to.shared.u64 t, %1; cvt.u32.u64 %0, t; }" : "=r"(a) : "l"(p));
    return a;
}
__device__ __forceinline__ void ldmatrix_x4(uint32_t& r0, uint32_t& r1,
                                            uint32_t& r2, uint32_t& r3, uint32_t addr) {
    asm volatile("ldmatrix.sync.aligned.m8n8.x4.shared.b16 {%0,%1,%2,%3}, [%4];"
                 : "=r"(r0), "=r"(r1), "=r"(r2), "=r"(r3) : "r"(addr));
}
__device__ __forceinline__ void mma_f16(float* d, const uint32_t* a,
                                        uint32_t b0, uint32_t b1) {
    asm volatile(
        "mma.sync.aligned.m16n8k16.row.col.f32.f16.f16.f32 "
        "{%0,%1,%2,%3}, {%4,%5,%6,%7}, {%8,%9}, {%0,%1,%2,%3};"
        : "+f"(d[0]), "+f"(d[1]), "+f"(d[2]), "+f"(d[3])
        : "r"(a[0]), "r"(a[1]), "r"(a[2]), "r"(a[3]), "r"(b0), "r"(b1));
}
__device__ __forceinline__ void cp16(uint32_t dst, const void* src) {
    asm volatile("cp.async.cg.shared.global [%0], [%1], 16;" :: "r"(dst), "l"(src));
}
#define CP_COMMIT() asm volatile("cp.async.commit_group;" ::: "memory")
#define CP_WAIT1()  asm volatile("cp.async.wait_group 1;" ::: "memory")

__device__ __forceinline__ uint32_t pack2(float a, float b) {
    __half2 h = __floats2half2_rn(a, b);
    return *reinterpret_cast<uint32_t*>(&h);
}

// ---------------------------------------------------------------------------
// Kernel 1 (fused): blocks [0,4096): per-batch partial sums.
//                   blocks [4096,5120): convert W -> g_Wh fp16 K-panels.
// ---------------------------------------------------------------------------
__global__ void reduce_conv_kernel(const float* __restrict__ x,
                                   const float* __restrict__ W) {
    if (blockIdx.x < BB * RED_CHUNKS) {
        const int b     = blockIdx.x / RED_CHUNKS;
        const int chunk = blockIdx.x % RED_CHUNKS;
        const int n4    = SC / RED_CHUNKS / 4;
        const float4* px = reinterpret_cast<const float4*>(x + (size_t)b * SC) + (size_t)chunk * n4;

        float s = 0.f, sq = 0.f;
        for (int i = threadIdx.x; i < n4; i += blockDim.x) {
            float4 v = px[i];
            s  += v.x + v.y + v.z + v.w;
            sq += v.x*v.x + v.y*v.y + v.z*v.z + v.w*v.w;
        }
        __shared__ float ss[8], ssq[8];
        #pragma unroll
        for (int o = 16; o > 0; o >>= 1) {
            s  += __shfl_down_sync(0xffffffff, s,  o);
            sq += __shfl_down_sync(0xffffffff, sq, o);
        }
        if ((threadIdx.x & 31) == 0) { ss[threadIdx.x >> 5] = s; ssq[threadIdx.x >> 5] = sq; }
        __syncthreads();
        if (threadIdx.x == 0) {
            float ts = 0.f, tsq = 0.f;
            #pragma unroll
            for (int w = 0; w < 8; w++) { ts += ss[w]; tsq += ssq[w]; }
            g_partials[blockIdx.x] = make_float2(ts, tsq);
        }
    } else {
        __shared__ float tile[32][33];
        const int cw = blockIdx.x - BB * RED_CHUNKS;   // 0..1023
        const int m0 = (cw >> 5) * 32;
        const int s0 = (cw & 31) * 32;
        const int tx = threadIdx.x & 31;
        const int ty = threadIdx.x >> 5;
        #pragma unroll
        for (int i = 0; i < 4; i++)
            tile[ty + i * 8][tx] = W[(size_t)(m0 + ty + i * 8) * SS + s0 + tx];
        __syncthreads();
        const int idx = threadIdx.x;
        if (idx < 128) {
            const int m     = idx >> 2;
            const int chunk = idx & 3;
            const int kt    = s0 >> 5;
            uint4 pk;
            pk.x = pack2(tile[m][chunk*8+0], tile[m][chunk*8+1]);
            pk.y = pack2(tile[m][chunk*8+2], tile[m][chunk*8+3]);
            pk.z = pack2(tile[m][chunk*8+4], tile[m][chunk*8+5]);
            pk.w = pack2(tile[m][chunk*8+6], tile[m][chunk*8+7]);
            *reinterpret_cast<uint4*>(g_Wh + ((size_t)kt * SS + m0 + m) * 32 + chunk * 8) = pk;
        }
    }
}

// ---------------------------------------------------------------------------
// Kernel 2: finalize stats (mu, rstd) per batch.
// ---------------------------------------------------------------------------
__global__ void stats_kernel() {
    int b = threadIdx.x;
    if (b < BB) {
        float s = 0.f, sq = 0.f;
        #pragma unroll 8
        for (int i = 0; i < RED_CHUNKS; i++) {
            float2 p = g_partials[b * RED_CHUNKS + i];
            s += p.x; sq += p.y;
        }
        float mu  = s / (float)SC;
        float var = fmaxf(sq / (float)SC - mu * mu, 0.f);
        g_stats[b] = make_float2(mu, rsqrtf(var + EPS));
    }
}

// ---------------------------------------------------------------------------
// Kernel 3: fused LayerNorm + transpose -> g_Hp K-panels [(kt*NN + n)*32 + ks].
// 32(s) x 64(c) tiles, block (64,4): all 256 threads active in BOTH phases.
// ---------------------------------------------------------------------------
__global__ void normalize_t_kernel(const float* __restrict__ x,
                                   const float* __restrict__ lnw,
                                   const float* __restrict__ lnb) {
    __shared__ float tile[32][65];     // [s_local][c_local]
    const int b  = blockIdx.z;
    const int s0 = blockIdx.x * 32;
    const int c0 = blockIdx.y * 64;
    const float2 st = g_stats[b];
    const int tx = threadIdx.x;        // 0..63
    const int ty = threadIdx.y;        // 0..3

    #pragma unroll
    for (int i = 0; i < 8; i++) {
        int sl = ty + i * 4;           // 0..31
        int s  = s0 + sl;
        int c  = c0 + tx;
        float v  = x  [(size_t)b * SC + (size_t)s * CC + c];
        float w  = lnw[(size_t)s * CC + c];
        float bb = lnb[(size_t)s * CC + c];
        tile[sl][tx] = (v - st.x) * st.y * w + bb;
    }
    __syncthreads();
    const int idx   = ty * 64 + tx;    // 0..255
    const int c     = idx >> 2;        // 0..63
    const int chunk = idx & 3;         // 0..3
    const int kt    = s0 >> 5;
    const int n     = b * CC + c0 + c;
    uint4 pk;
    pk.x = pack2(tile[chunk*8+0][c], tile[chunk*8+1][c]);
    pk.y = pack2(tile[chunk*8+2][c], tile[chunk*8+3][c]);
    pk.z = pack2(tile[chunk*8+4][c], tile[chunk*8+5][c]);
    pk.w = pack2(tile[chunk*8+6][c], tile[chunk*8+7][c]);
    *reinterpret_cast<uint4*>(g_Hp + ((size_t)kt * NN + n) * 32 + chunk * 8) = pk;
}

// ---------------------------------------------------------------------------
// Kernel 4: fp16 GEMM, fp32 acc. D[1024, 32768] = Wh x Hp^T, K=1024.
// CTA 128(M) x 128(N) x 32(K). 128 threads, 4 warps (2M x 2N), warp 64x64.
// Register fragment double-buffer (hides LDSM). 2 CTAs/SM. 3-stage cp.async.
// 80B smem rows (conflict-free ldmatrix).   [R11 mainloop — verbatim]
// Epilogue: out = x + relu(D + bias) with STREAMING hints (__ldcs/__stcs) so
// the 256MB epilogue traffic does not evict the L2-resident B panels (64MB).
// ---------------------------------------------------------------------------
#define BM 128
#define BN 128
#define AST (BM * 80)              // 10240 B per A stage
#define BST (BN * 80)              // 10240 B per B stage
#define NSTG 3
#define OFF_BS (NSTG * AST)        // B stages base
#define GSMEM (NSTG * (AST + BST)) // 61440 B -> 2 CTAs = 120KB

__global__ __launch_bounds__(128, 2)
void gemm_f16(const float* __restrict__ linb,
              const float* __restrict__ x, float* __restrict__ out)
{
    extern __shared__ char smem[];
    const uint32_t sb = smem_to_u32(smem);

    const int tid  = threadIdx.x;
    const int lane = tid & 31;
    const int wid  = tid >> 5;          // 0..3
    const int wm   = (wid >> 1) * 64;   // 0 / 64
    const int wn   = (wid & 1) * 64;    // 0 / 64
    const int m0   = blockIdx.x * BM;
    const int n0   = blockIdx.y * BN;

    float acc[4][8][4];
    #pragma unroll
    for (int i = 0; i < 4; i++)
        #pragma unroll
        for (int j = 0; j < 8; j++)
            #pragma unroll
            for (int k = 0; k < 4; k++) acc[i][j][k] = 0.f;

    const __half* Apan = g_Wh + ((size_t)m0) * 32;  // + t*SS*32 per tile
    const __half* Bpan = g_Hp + ((size_t)n0) * 32;  // + t*NN*32 per tile

    // cp.async: 512 A tasks + 512 B tasks over 128 threads = 4+4 per thread.
    #define ISSUE(t, st)                                                          \
        do {                                                                      \
            const __half* asrc = Apan + (size_t)(t) * SS * 32;                    \
            const __half* bsrc = Bpan + (size_t)(t) * NN * 32;                    \
            _Pragma("unroll")                                                     \
            for (int k = 0; k < 4; k++) {                                         \
                int idx = k * 128 + tid;                                          \
                int row = idx >> 2, ch = idx & 3;                                 \
                cp16(sb + (st) * AST + row * 80 + ch * 16,                        \
                     asrc + (size_t)row * 32 + ch * 8);                           \
                cp16(sb + OFF_BS + (st) * BST + row * 80 + ch * 16,               \
                     bsrc + (size_t)row * 32 + ch * 8);                           \
            }                                                                     \
        } while (0)

    // ldmatrix base addresses
    const int l15 = lane & 15;
    const int lhi = lane >> 4;
    const uint32_t aLd = sb + (wm + l15) * 80 + lhi * 16;
    const uint32_t bLd = sb + OFF_BS + (wn + l15) * 80 + lhi * 16;

    // fragment double buffers
    uint32_t af[2][16], bf[2][16];

    #define LOAD_FRAGS(buf, st, ks)                                               \
        do {                                                                      \
            _Pragma("unroll")                                                     \
            for (int i = 0; i < 4; i++)                                           \
                ldmatrix_x4(af[buf][i*4+0], af[buf][i*4+1],                       \
                            af[buf][i*4+2], af[buf][i*4+3],                       \
                            aLd + (st) * AST + i * 16 * 80 + (ks) * 32);          \
            _Pragma("unroll")                                                     \
            for (int j = 0; j < 4; j++)                                           \
                ldmatrix_x4(bf[buf][j*4+0], bf[buf][j*4+1],                       \
                            bf[buf][j*4+2], bf[buf][j*4+3],                       \
                            bLd + (st) * BST + j * 16 * 80 + (ks) * 32);          \
        } while (0)

    #define MMA_ALL(buf)                                                          \
        do {                                                                      \
            _Pragma("unroll")                                                     \
            for (int i = 0; i < 4; i++)                                           \
                _Pragma("unroll")                                                 \
                for (int j = 0; j < 4; j++) {                                     \
                    mma_f16(acc[i][2*j    ], &af[buf][i*4],                       \
                            bf[buf][j*4+0], bf[buf][j*4+2]);                      \
                    mma_f16(acc[i][2*j + 1], &af[buf][i*4],                       \
                            bf[buf][j*4+1], bf[buf][j*4+3]);                      \
                }                                                                 \
        } while (0)

    // prologue: stages 0,1 in flight; stage 0 ready; frags(buf0, ks=0) loaded.
    ISSUE(0, 0); CP_COMMIT();
    ISSUE(1, 1); CP_COMMIT();
    CP_WAIT1();
    __syncthreads();
    LOAD_FRAGS(0, 0, 0);

    for (int t = 0; t < NT; t++) {
        const int st = t % 3;

        // ks = 0 phase: prefetch ks=1 frags, then MMA on ks=0 frags.
        LOAD_FRAGS(1, st, 1);
        MMA_ALL(0);

        // ks = 1 phase: keep gmem pipe fed, advance stage, prefetch next
        // tile's ks=0 frags, then MMA on ks=1 frags.
        if (t + 2 < NT) ISSUE(t + 2, (t + 2) % 3);
        CP_COMMIT();                // unconditional: keeps wait_group ledger
        if (t + 1 < NT) {
            CP_WAIT1();             // tile t+1's stage complete
            __syncthreads();        // all warps past stage-(t-1) frag reads
            LOAD_FRAGS(0, (t + 1) % 3, 0);
        }
        MMA_ALL(1);
    }

    // Epilogue (STREAMING): n -> (batch, channel); whole CTA in one batch.
    const int bidx = n0 >> 9;
    const int c0   = n0 & 511;
    const float* xb = x   + (size_t)bidx * SC;
    float*       ob = out + (size_t)bidx * SC;

    #pragma unroll
    for (int i = 0; i < 4; i++) {
        const int t0 = m0 + wm + i * 16 + (lane >> 2);
        const float bias0 = __ldg(linb + t0);
        const float bias1 = __ldg(linb + t0 + 8);
        #pragma unroll
        for (int j = 0; j < 8; j++) {
            const int c = c0 + wn + j * 8 + (lane & 3) * 2;
            float2 xv0 = __ldcs(reinterpret_cast<const float2*>(xb + (size_t)t0 * CC + c));
            float2 o0;
            o0.x = xv0.x + fmaxf(acc[i][j][0] + bias0, 0.f);
            o0.y = xv0.y + fmaxf(acc[i][j][1] + bias0, 0.f);
            __stcs(reinterpret_cast<float2*>(ob + (size_t)t0 * CC + c), o0);

            float2 xv1 = __ldcs(reinterpret_cast<const float2*>(xb + (size_t)(t0 + 8) * CC + c));
            float2 o1;
            o1.x = xv1.x + fmaxf(acc[i][j][2] + bias1, 0.f);
            o1.y = xv1.y + fmaxf(acc[i][j][3] + bias1, 0.f);
            __stcs(reinterpret_cast<float2*>(ob + (size_t)(t0 + 8) * CC + c), o1);
        }
    }
}

// ---------------------------------------------------------------------------
// Launch (4 kernels so ncu -s 5 -c 1 lands on the GEMM)
// ---------------------------------------------------------------------------
extern "C" void kernel_launch(void* const* d_in, const int* in_sizes, int n_in,
                              void* d_out, int out_size) {
    const float* x     = (const float*)d_in[0];
    const float* ln_w  = (const float*)d_in[1];
    const float* ln_b  = (const float*)d_in[2];
    const float* lin_w = (const float*)d_in[3];
    const float* lin_b = (const float*)d_in[4];
    float* out = (float*)d_out;

    cudaFuncSetAttribute(gemm_f16, cudaFuncAttributeMaxDynamicSharedMemorySize, GSMEM);

    reduce_conv_kernel<<<BB * RED_CHUNKS + 1024, 256>>>(x, lin_w);
    stats_kernel<<<1, 64>>>();
    normalize_t_kernel<<<dim3(SS / 32, CC / 64, BB), dim3(64, 4)>>>(x, ln_w, ln_b);

    // M=1024 (8 x 128), N=32768 (256 x 128)
    gemm_f16<<<dim3(8, 256), 128, GSMEM>>>(lin_b, x, out);
}

// round 16
// speedup vs baseline: 1.5621x; 1.5621x over previous
#include <cuda_runtime.h>
#include <cuda_fp16.h>
#include <cstdint>

// Problem constants
#define BB 64
#define SS 1024
#define CC 512
#define SC (SS*CC)
#define NN (BB*CC)          // 32768 = total N of the big GEMM
#define EPS 1e-5f
#define RED_CHUNKS 32
#define BK 32               // k-tile (halves)
#define NT (SS / BK)        // 32 k-tiles

// Scratch (device globals; 16B-aligned for cp.async / uint4)
__device__ float2 g_partials[BB * RED_CHUNKS];
__device__ float2 g_stats[BB];
// K-panel layouts: [(kt*ROWS + row)*32 + ks], fp16
__device__ __align__(16) __half g_Hp[(size_t)NN * SS];     // B panels (64MB)
__device__ __align__(16) __half g_Wh[(size_t)SS * SS];     // A panels (2MB)

// ---------------------------------------------------------------------------
// helpers
// ---------------------------------------------------------------------------
__device__ __forceinline__ uint32_t smem_to_u32(const void* p) {
    uint32_t a;
    asm("{ .reg .u64 t; cvta.to.shared.u64 t, %1; cvt.u32.u64 %0, t; }" : "=r"(a) : "l"(p));
    return a;
}
__device__ __forceinline__ void ldmatrix_x4(uint32_t& r0, uint32_t& r1,
                                            uint32_t& r2, uint32_t& r3, uint32_t addr) {
    asm volatile("ldmatrix.sync.aligned.m8n8.x4.shared.b16 {%0,%1,%2,%3}, [%4];"
                 : "=r"(r0), "=r"(r1), "=r"(r2), "=r"(r3) : "r"(addr));
}
__device__ __forceinline__ void mma_f16(float* d, const uint32_t* a,
                                        uint32_t b0, uint32_t b1) {
    asm volatile(
        "mma.sync.aligned.m16n8k16.row.col.f32.f16.f16.f32 "
        "{%0,%1,%2,%3}, {%4,%5,%6,%7}, {%8,%9}, {%0,%1,%2,%3};"
        : "+f"(d[0]), "+f"(d[1]), "+f"(d[2]), "+f"(d[3])
        : "r"(a[0]), "r"(a[1]), "r"(a[2]), "r"(a[3]), "r"(b0), "r"(b1));
}
__device__ __forceinline__ void cp16(uint32_t dst, const void* src) {
    asm volatile("cp.async.cg.shared.global [%0], [%1], 16;" :: "r"(dst), "l"(src));
}
#define CP_COMMIT() asm volatile("cp.async.commit_group;" ::: "memory")
#define CP_WAIT1()  asm volatile("cp.async.wait_group 1;" ::: "memory")

__device__ __forceinline__ uint32_t pack2(float a, float b) {
    __half2 h = __floats2half2_rn(a, b);
    return *reinterpret_cast<uint32_t*>(&h);
}

// ---------------------------------------------------------------------------
// Kernel 1 (fused): blocks [0, 2048): per-batch partial sums (512 threads,
//   32 chunks/batch -> higher per-block MLP than the 256-thread version).
//                   blocks [2048, 3072): convert W -> g_Wh fp16 K-panels.
// ---------------------------------------------------------------------------
__global__ void reduce_conv_kernel(const float* __restrict__ x,
                                   const float* __restrict__ W) {
    if (blockIdx.x < BB * RED_CHUNKS) {
        const int b     = blockIdx.x / RED_CHUNKS;
        const int chunk = blockIdx.x % RED_CHUNKS;
        const int n4    = SC / RED_CHUNKS / 4;   // 4096 float4 per block
        const float4* px = reinterpret_cast<const float4*>(x + (size_t)b * SC) + (size_t)chunk * n4;

        float s = 0.f, sq = 0.f;
        #pragma unroll 4
        for (int i = threadIdx.x; i < n4; i += blockDim.x) {
            float4 v = px[i];
            s  += v.x + v.y + v.z + v.w;
            sq += v.x*v.x + v.y*v.y + v.z*v.z + v.w*v.w;
        }
        __shared__ float ss[16], ssq[16];
        #pragma unroll
        for (int o = 16; o > 0; o >>= 1) {
            s  += __shfl_down_sync(0xffffffff, s,  o);
            sq += __shfl_down_sync(0xffffffff, sq, o);
        }
        if ((threadIdx.x & 31) == 0) { ss[threadIdx.x >> 5] = s; ssq[threadIdx.x >> 5] = sq; }
        __syncthreads();
        if (threadIdx.x == 0) {
            float ts = 0.f, tsq = 0.f;
            #pragma unroll
            for (int w = 0; w < 16; w++) { ts += ss[w]; tsq += ssq[w]; }
            g_partials[blockIdx.x] = make_float2(ts, tsq);
        }
    } else {
        // convert W (fp32 [m][s]) -> g_Wh fp16 K-panels [(kt*1024+m)*32+ks]
        __shared__ float tile[32][33];
        const int cw = blockIdx.x - BB * RED_CHUNKS;   // 0..1023
        const int m0 = (cw >> 5) * 32;
        const int s0 = (cw & 31) * 32;
        const int tx = threadIdx.x & 31;
        const int ty = threadIdx.x >> 5;               // 0..15
        #pragma unroll
        for (int i = 0; i < 2; i++)
            tile[ty + i * 16][tx] = W[(size_t)(m0 + ty + i * 16) * SS + s0 + tx];
        __syncthreads();
        const int idx = threadIdx.x;
        if (idx < 128) {
            const int m     = idx >> 2;
            const int chunk = idx & 3;
            const int kt    = s0 >> 5;
            uint4 pk;
            pk.x = pack2(tile[m][chunk*8+0], tile[m][chunk*8+1]);
            pk.y = pack2(tile[m][chunk*8+2], tile[m][chunk*8+3]);
            pk.z = pack2(tile[m][chunk*8+4], tile[m][chunk*8+5]);
            pk.w = pack2(tile[m][chunk*8+6], tile[m][chunk*8+7]);
            *reinterpret_cast<uint4*>(g_Wh + ((size_t)kt * SS + m0 + m) * 32 + chunk * 8) = pk;
        }
    }
}

// ---------------------------------------------------------------------------
// Kernel 2: finalize stats (mu, rstd) per batch.
// ---------------------------------------------------------------------------
__global__ void stats_kernel() {
    int b = threadIdx.x;
    if (b < BB) {
        float s = 0.f, sq = 0.f;
        #pragma unroll 8
        for (int i = 0; i < RED_CHUNKS; i++) {
            float2 p = g_partials[b * RED_CHUNKS + i];
            s += p.x; sq += p.y;
        }
        float mu  = s / (float)SC;
        float var = fmaxf(sq / (float)SC - mu * mu, 0.f);
        g_stats[b] = make_float2(mu, rsqrtf(var + EPS));
    }
}

// ---------------------------------------------------------------------------
// Kernel 3: fused LayerNorm + transpose -> g_Hp K-panels [(kt*NN + n)*32 + ks].
// 64(s) x 64(c) tiles, block (64,8) = 512 threads, ALL active in both phases.
// Each thread: 8 coalesced loads, 1 uint4 packed store (spans 2 k-panels).
// grid (S/64, C/64, B).
// ---------------------------------------------------------------------------
__global__ void normalize_t_kernel(const float* __restrict__ x,
                                   const float* __restrict__ lnw,
                                   const float* __restrict__ lnb) {
    __shared__ float tile[64][65];     // [s_local][c_local] (16.6KB)
    const int b  = blockIdx.z;
    const int s0 = blockIdx.x * 64;
    const int c0 = blockIdx.y * 64;
    const float2 st = g_stats[b];
    const int tx = threadIdx.x;        // 0..63
    const int ty = threadIdx.y;        // 0..7

    #pragma unroll
    for (int i = 0; i < 8; i++) {
        int sl = ty + i * 8;           // 0..63
        int s  = s0 + sl;
        int c  = c0 + tx;
        float v  = x  [(size_t)b * SC + (size_t)s * CC + c];
        float w  = lnw[(size_t)s * CC + c];
        float bb = lnb[(size_t)s * CC + c];
        tile[sl][tx] = (v - st.x) * st.y * w + bb;
    }
    __syncthreads();
    const int idx   = ty * 64 + tx;    // 0..511
    const int c     = idx >> 3;        // 0..63
    const int chunk = idx & 7;         // 0..7 (8 s-values each = 64 s total)
    const int kt    = (s0 >> 5) + (chunk >> 2);   // two k-panels per s-tile
    const int c4    = chunk & 3;
    const int n     = b * CC + c0 + c;
    uint4 pk;
    pk.x = pack2(tile[chunk*8+0][c], tile[chunk*8+1][c]);
    pk.y = pack2(tile[chunk*8+2][c], tile[chunk*8+3][c]);
    pk.z = pack2(tile[chunk*8+4][c], tile[chunk*8+5][c]);
    pk.w = pack2(tile[chunk*8+6][c], tile[chunk*8+7][c]);
    *reinterpret_cast<uint4*>(g_Hp + ((size_t)kt * NN + n) * 32 + c4 * 8) = pk;
}

// ---------------------------------------------------------------------------
// Kernel 4: fp16 GEMM, fp32 acc. D[1024, 32768] = Wh x Hp^T, K=1024.
// CTA 128(M) x 128(N) x 32(K). 128 threads, 4 warps (2M x 2N), warp 64x64.
// Register fragment double-buffer (hides LDSM). 2 CTAs/SM. 3-stage cp.async.
// 80B smem rows (conflict-free ldmatrix).   [R11 — byte-identical, frozen]
// Epilogue: out = x + relu(D + bias), plain loads/stores (R15 streaming
// hints regressed 210->346us; reverted).
// ---------------------------------------------------------------------------
#define BM 128
#define BN 128
#define AST (BM * 80)              // 10240 B per A stage
#define BST (BN * 80)              // 10240 B per B stage
#define NSTG 3
#define OFF_BS (NSTG * AST)        // B stages base
#define GSMEM (NSTG * (AST + BST)) // 61440 B -> 2 CTAs = 120KB

__global__ __launch_bounds__(128, 2)
void gemm_f16(const float* __restrict__ linb,
              const float* __restrict__ x, float* __restrict__ out)
{
    extern __shared__ char smem[];
    const uint32_t sb = smem_to_u32(smem);

    const int tid  = threadIdx.x;
    const int lane = tid & 31;
    const int wid  = tid >> 5;          // 0..3
    const int wm   = (wid >> 1) * 64;   // 0 / 64
    const int wn   = (wid & 1) * 64;    // 0 / 64
    const int m0   = blockIdx.x * BM;
    const int n0   = blockIdx.y * BN;

    float acc[4][8][4];
    #pragma unroll
    for (int i = 0; i < 4; i++)
        #pragma unroll
        for (int j = 0; j < 8; j++)
            #pragma unroll
            for (int k = 0; k < 4; k++) acc[i][j][k] = 0.f;

    const __half* Apan = g_Wh + ((size_t)m0) * 32;  // + t*SS*32 per tile
    const __half* Bpan = g_Hp + ((size_t)n0) * 32;  // + t*NN*32 per tile

    // cp.async: 512 A tasks + 512 B tasks over 128 threads = 4+4 per thread.
    #define ISSUE(t, st)                                                          \
        do {                                                                      \
            const __half* asrc = Apan + (size_t)(t) * SS * 32;                    \
            const __half* bsrc = Bpan + (size_t)(t) * NN * 32;                    \
            _Pragma("unroll")                                                     \
            for (int k = 0; k < 4; k++) {                                         \
                int idx = k * 128 + tid;                                          \
                int row = idx >> 2, ch = idx & 3;                                 \
                cp16(sb + (st) * AST + row * 80 + ch * 16,                        \
                     asrc + (size_t)row * 32 + ch * 8);                           \
                cp16(sb + OFF_BS + (st) * BST + row * 80 + ch * 16,               \
                     bsrc + (size_t)row * 32 + ch * 8);                           \
            }                                                                     \
        } while (0)

    // ldmatrix base addresses
    const int l15 = lane & 15;
    const int lhi = lane >> 4;
    const uint32_t aLd = sb + (wm + l15) * 80 + lhi * 16;
    const uint32_t bLd = sb + OFF_BS + (wn + l15) * 80 + lhi * 16;

    // fragment double buffers
    uint32_t af[2][16], bf[2][16];

    #define LOAD_FRAGS(buf, st, ks)                                               \
        do {                                                                      \
            _Pragma("unroll")                                                     \
            for (int i = 0; i < 4; i++)                                           \
                ldmatrix_x4(af[buf][i*4+0], af[buf][i*4+1],                       \
                            af[buf][i*4+2], af[buf][i*4+3],                       \
                            aLd + (st) * AST + i * 16 * 80 + (ks) * 32);          \
            _Pragma("unroll")                                                     \
            for (int j = 0; j < 4; j++)                                           \
                ldmatrix_x4(bf[buf][j*4+0], bf[buf][j*4+1],                       \
                            bf[buf][j*4+2], bf[buf][j*4+3],                       \
                            bLd + (st) * BST + j * 16 * 80 + (ks) * 32);          \
        } while (0)

    #define MMA_ALL(buf)                                                          \
        do {                                                                      \
            _Pragma("unroll")                                                     \
            for (int i = 0; i < 4; i++)                                           \
                _Pragma("unroll")                                                 \
                for (int j = 0; j < 4; j++) {                                     \
                    mma_f16(acc[i][2*j    ], &af[buf][i*4],                       \
                            bf[buf][j*4+0], bf[buf][j*4+2]);                      \
                    mma_f16(acc[i][2*j + 1], &af[buf][i*4],                       \
                            bf[buf][j*4+1], bf[buf][j*4+3]);                      \
                }                                                                 \
        } while (0)

    // prologue: stages 0,1 in flight; stage 0 ready; frags(buf0, ks=0) loaded.
    ISSUE(0, 0); CP_COMMIT();
    ISSUE(1, 1); CP_COMMIT();
    CP_WAIT1();
    __syncthreads();
    LOAD_FRAGS(0, 0, 0);

    for (int t = 0; t < NT; t++) {
        const int st = t % 3;

        // ks = 0 phase: prefetch ks=1 frags, then MMA on ks=0 frags.
        LOAD_FRAGS(1, st, 1);
        MMA_ALL(0);

        // ks = 1 phase: keep gmem pipe fed, advance stage, prefetch next
        // tile's ks=0 frags, then MMA on ks=1 frags.
        if (t + 2 < NT) ISSUE(t + 2, (t + 2) % 3);
        CP_COMMIT();                // unconditional: keeps wait_group ledger
        if (t + 1 < NT) {
            CP_WAIT1();             // tile t+1's stage complete
            __syncthreads();        // all warps past stage-(t-1) frag reads
            LOAD_FRAGS(0, (t + 1) % 3, 0);
        }
        MMA_ALL(1);
    }

    // Epilogue: n -> (batch, channel); whole CTA sits in one batch.
    const int bidx = n0 >> 9;
    const int c0   = n0 & 511;
    const float* xb = x   + (size_t)bidx * SC;
    float*       ob = out + (size_t)bidx * SC;

    #pragma unroll
    for (int i = 0; i < 4; i++) {
        const int t0 = m0 + wm + i * 16 + (lane >> 2);
        const float bias0 = __ldg(linb + t0);
        const float bias1 = __ldg(linb + t0 + 8);
        #pragma unroll
        for (int j = 0; j < 8; j++) {
            const int c = c0 + wn + j * 8 + (lane & 3) * 2;
            float2 xv0 = *reinterpret_cast<const float2*>(xb + (size_t)t0 * CC + c);
            float2 o0;
            o0.x = xv0.x + fmaxf(acc[i][j][0] + bias0, 0.f);
            o0.y = xv0.y + fmaxf(acc[i][j][1] + bias0, 0.f);
            *reinterpret_cast<float2*>(ob + (size_t)t0 * CC + c) = o0;

            float2 xv1 = *reinterpret_cast<const float2*>(xb + (size_t)(t0 + 8) * CC + c);
            float2 o1;
            o1.x = xv1.x + fmaxf(acc[i][j][2] + bias1, 0.f);
            o1.y = xv1.y + fmaxf(acc[i][j][3] + bias1, 0.f);
            *reinterpret_cast<float2*>(ob + (size_t)(t0 + 8) * CC + c) = o1;
        }
    }
}

// ---------------------------------------------------------------------------
// Launch (4 kernels so ncu -s 5 -c 1 lands on the GEMM)
// ---------------------------------------------------------------------------
extern "C" void kernel_launch(void* const* d_in, const int* in_sizes, int n_in,
                              void* d_out, int out_size) {
    const float* x     = (const float*)d_in[0];
    const float* ln_w  = (const float*)d_in[1];
    const float* ln_b  = (const float*)d_in[2];
    const float* lin_w = (const float*)d_in[3];
    const float* lin_b = (const float*)d_in[4];
    float* out = (float*)d_out;

    cudaFuncSetAttribute(gemm_f16, cudaFuncAttributeMaxDynamicSharedMemorySize, GSMEM);

    reduce_conv_kernel<<<BB * RED_CHUNKS + 1024, 512>>>(x, lin_w);
    stats_kernel<<<1, 64>>>();
    normalize_t_kernel<<<dim3(SS / 64, CC / 64, BB), dim3(64, 8)>>>(x, ln_w, ln_b);

    // M=1024 (8 x 128), N=32768 (256 x 128)
    gemm_f16<<<dim3(8, 256), 128, GSMEM>>>(lin_b, x, out);
}